// round 9
// baseline (speedup 1.0000x reference)
#include <cuda_runtime.h>
#include <cuda_bf16.h>
#include <math.h>

// CropRoi: f (B=4, C=64, 32,32,32) f32; proposals (N,8) [b,score,cx,cy,cz,sx,sy,sz]
// out (N,C,7,7,7) f32. dims_max=32, R=7.
// Proven invariants: L = c1-c0 in [2,13]; every per-axis bin window width in [1,3].
//
// Plan: block = (proposal, 4-channel group).
//  Phase 1: stage raw crop region to smem. Each (d,h) row of f is one aligned
//           128B line -> 1 coalesced LDG wavefront per row per channel
//           (~330 wavefronts/block vs ~1700 for direct gathers).
//  Phase 2: 343 threads pool from smem (pitch-17 rows -> ~conflict-free LDS),
//           w-window unrolled via clamp-duplicate (max is idempotent).

#define R_BINS 7
#define C_CH   64
#define DIMMAX 32
#define CG     4
#define NW     11
#define NTHREADS 352
#define MAXL   13
#define PITCH  17
#define CHS    (MAXL * MAXL * PITCH)   // 2873 floats per channel slab

__global__ __launch_bounds__(NTHREADS) void crop_roi_kernel(
        const float* __restrict__ f,
        const float* __restrict__ props,
        float* __restrict__ out) {
    const int n    = blockIdx.x;
    const int cb   = blockIdx.y * CG;
    const int tid  = threadIdx.x;
    const int lane = tid & 31;
    const int warp = tid >> 5;

    __shared__ int sS[3][R_BINS], sE[3][R_BINS];
    __shared__ int sC0[3], sL[3], sB;
    __shared__ float sm[CG * CHS];     // 4*2873*4B = 45968B < 48KB

    // ---- bounds (21 threads), bitwise-identical to reference math ----
    if (tid < 3 * R_BINS) {
        const int ax = tid / R_BINS;
        const int bi = tid - ax * R_BINS;
        const float* p = props + (size_t)n * 8;
        if (tid == 0) sB = (int)p[0];
        float center = __ldg(p + 2 + ax);
        float side   = __ldg(p + 5 + ax);
        // *0.5f / *0.25f exact (powers of two) -> matches jnp bit-for-bit
        int c0 = (int)floorf((center - 0.5f * side) * 0.25f);
        int c1 = (int)ceilf ((center + 0.5f * side) * 0.25f);
        c0 = max(c0, 0);
        c1 = min(c1, DIMMAX);
        int L  = c1 - c0;
        int ss = c0 + (bi * L) / R_BINS;                     // floor div
        int ee = c0 + ((bi + 1) * L + R_BINS - 1) / R_BINS;  // ceil div
        ee = min(ee, ss + 6);                                // K cap (safety)
        sS[ax][bi] = ss;
        sE[ax][bi] = ee;
        if (bi == 0) { sC0[ax] = c0; sL[ax] = L; }
    }
    __syncthreads();

    const int c0d = sC0[0], c0h = sC0[1], c0w = sC0[2];
    const int Ld  = sL[0],  Lh  = sL[1],  Lw  = sL[2];
    const int nrows = Ld * Lh;
    const float* base = f + (((size_t)sB * C_CH + cb) << 15);  // 32^3 per (b,c)

    // ---- phase 1: coalesced staging (one line-wavefront per row per ch) ----
    const unsigned Mdiv = (1u << 20) / (unsigned)Lh + 1u;   // exact for r<196, Lh<=13
    for (int r = warp; r < nrows; r += NW) {
        int dd = (int)(((unsigned)r * Mdiv) >> 20);
        int hh = r - dd * Lh;
        const float* g = base + ((c0d + dd) << 10) + ((c0h + hh) << 5) + c0w;
        float* s = sm + (dd * MAXL + hh) * PITCH + lane;
        if (lane < Lw) {
            float v0 = g[lane];
            float v1 = g[lane + 1 * 32768];
            float v2 = g[lane + 2 * 32768];
            float v3 = g[lane + 3 * 32768];
            s[0 * CHS] = v0;
            s[1 * CHS] = v1;
            s[2 * CHS] = v2;
            s[3 * CHS] = v3;
        }
    }
    __syncthreads();

    // ---- phase 2: pool from smem ----
    if (tid < 343) {
        const int i   = tid / 49;
        const int rem = tid - i * 49;
        const int j   = rem / 7;
        const int k   = rem - j * 7;

        const int ds = sS[0][i] - c0d, de = sE[0][i] - c0d;
        const int hs = sS[1][j] - c0h, he = sE[1][j] - c0h;
        const int w0 = sS[2][k] - c0w;
        const int wl = sE[2][k] - 1 - c0w;
        const int w1 = min(w0 + 1, wl);
        const int w2 = min(w0 + 2, wl);

        float m0 = -3.402823466e+38f;   // finfo(float32).min
        float m1 = m0, m2 = m0, m3 = m0;

        for (int d = ds; d < de; d++) {
            for (int h = hs; h < he; h++) {
                const float* sp = sm + (d * MAXL + h) * PITCH;
                // w-window clamp-duplicated: unconditional 3 reads, max-idempotent
                float a0 = fmaxf(fmaxf(sp[w0], sp[w1]), sp[w2]);
                sp += CHS;
                float a1 = fmaxf(fmaxf(sp[w0], sp[w1]), sp[w2]);
                sp += CHS;
                float a2 = fmaxf(fmaxf(sp[w0], sp[w1]), sp[w2]);
                sp += CHS;
                float a3 = fmaxf(fmaxf(sp[w0], sp[w1]), sp[w2]);
                m0 = fmaxf(m0, a0);
                m1 = fmaxf(m1, a1);
                m2 = fmaxf(m2, a2);
                m3 = fmaxf(m3, a3);
            }
        }

        size_t o = ((size_t)n * C_CH + cb) * 343 + tid;
        out[o]           = m0;
        out[o + 343]     = m1;
        out[o + 2 * 343] = m2;
        out[o + 3 * 343] = m3;
    }
}

extern "C" void kernel_launch(void* const* d_in, const int* in_sizes, int n_in,
                              void* d_out, int out_size) {
    const float* f     = (const float*)d_in[0];
    const float* props = (const float*)d_in[2];
    float* out = (float*)d_out;

    int n_props = in_sizes[2] / 8;
    dim3 grid(n_props, C_CH / CG);
    crop_roi_kernel<<<grid, NTHREADS>>>(f, props, out);
}